// round 5
// baseline (speedup 1.0000x reference)
#include <cuda_runtime.h>
#include <cuda_bf16.h>
#include <stdint.h>

#define MAXN 50000
#define MAXE 800000
#define DH 128

// ---------------- device scratch (no allocs allowed; 16B-aligned for float4) ----
__device__ __align__(16) int   g_hist[MAXN];
__device__ __align__(16) int   g_cnt[MAXN];
__device__ __align__(16) int   g_rowptr[MAXN + 1];
__device__ __align__(16) int   g_esrc[MAXE];
__device__ __align__(16) float g_dis[MAXN];
__device__ __align__(16) float g_h[(size_t)MAXN * DH];   // hs1, later hs2 (reused)
__device__ __align__(16) float g_x1[(size_t)MAXN * DH];  // relu output of layer 1
__device__ int g_is64;

// edge_index dtype detection: if data is really int64, upper 32-bit words of the
// first elements are all zero; if int32, those words hold real indices (nonzero).
__global__ void detect_kernel(const int* __restrict__ ei32, int E) {
    __shared__ int found;
    if (threadIdx.x == 0) found = 0;
    __syncthreads();
    int lim = min(4096, E);
    int nz = 0;
    for (int i = threadIdx.x; i < lim; i += blockDim.x) nz |= ei32[2 * i + 1];
    if (nz) atomicOr(&found, 1);
    __syncthreads();
    if (threadIdx.x == 0) g_is64 = (found == 0) ? 1 : 0;
}

__device__ __forceinline__ int load_idx(const void* ei, int E, int which, int i) {
    // which: 0 = src row, 1 = dst row
    if (g_is64) {
        const long long* p = (const long long*)ei;
        return (int)p[(size_t)which * E + i];
    } else {
        const int* p = (const int*)ei;
        return p[(size_t)which * E + i];
    }
}

// ---------------- graph preprocessing ----------------
__global__ void zero_kernel(int n) {
    int i = blockIdx.x * blockDim.x + threadIdx.x;
    if (i < n) { g_hist[i] = 0; g_cnt[i] = 0; }
}

__global__ void hist_kernel(const void* __restrict__ ei, int E) {
    int i = blockIdx.x * blockDim.x + threadIdx.x;
    int stride = gridDim.x * blockDim.x;
    for (; i < E; i += stride) {
        int d = load_idx(ei, E, 1, i);
        if (d >= 0 && d < MAXN) atomicAdd(&g_hist[d], 1);
    }
}

__global__ void dis_kernel(int n) {
    int i = blockIdx.x * blockDim.x + threadIdx.x;
    if (i < n) {
        // degree = in-degree + 1 (self loop); always >= 1
        g_dis[i] = rsqrtf((float)(g_hist[i] + 1));
    }
}

// single-block exclusive scan of g_hist -> g_rowptr (n up to ~50k)
__global__ void scan_kernel(int n) {
    __shared__ int sums[1024];
    int tid = threadIdx.x;
    int chunk = (n + 1023) >> 10;
    int b = tid * chunk;
    int e = min(b + chunk, n);
    int s = 0;
    for (int i = b; i < e; i++) s += g_hist[i];
    sums[tid] = s;
    __syncthreads();
    // Kogge-Stone inclusive scan
    for (int off = 1; off < 1024; off <<= 1) {
        int v = (tid >= off) ? sums[tid - off] : 0;
        __syncthreads();
        sums[tid] += v;
        __syncthreads();
    }
    int run = (tid > 0) ? sums[tid - 1] : 0;   // exclusive prefix
    for (int i = b; i < e; i++) { g_rowptr[i] = run; run += g_hist[i]; }
    if (b < n && e == n) g_rowptr[n] = run;
}

__global__ void scatter_kernel(const void* __restrict__ ei, int E) {
    int i = blockIdx.x * blockDim.x + threadIdx.x;
    int stride = gridDim.x * blockDim.x;
    for (; i < E; i += stride) {
        int d = load_idx(ei, E, 1, i);
        if (d < 0 || d >= MAXN) continue;
        int pos = g_rowptr[d] + atomicAdd(&g_cnt[d], 1);
        int s = load_idx(ei, E, 0, i);
        if (pos >= 0 && pos < MAXE) g_esrc[pos] = s;
    }
}

// ---------------- GEMM: g_h[m, 0..127] = dis[m] * (A[m,:] @ W) ----------------
// A = input pointer if Aext != nullptr, else g_x1 (layer 2).
// Tiling: BM=128, BN=128, BK=16, 256 threads, 8x8 microtile per thread.
__global__ void __launch_bounds__(256, 2)
gemm128(const float* __restrict__ Aext, const float* __restrict__ W,
        int M, int K) {
    __shared__ float As[16][128];
    __shared__ float Bs[16][128];

    const float* A = Aext ? Aext : (const float*)g_x1;
    float* C = (float*)g_h;

    const int tid = threadIdx.x;
    const int trow = (tid >> 4) << 3;      // 0..120
    const int tcol = (tid & 15) << 3;      // 0..120
    const int block_row = blockIdx.x * 128;

    const int a_r = tid >> 1;
    const int a_k = (tid & 1) << 3;
    const int b_k = tid >> 4;
    const int b_c = (tid & 15) << 3;

    float acc[8][8];
#pragma unroll
    for (int i = 0; i < 8; i++)
#pragma unroll
        for (int j = 0; j < 8; j++) acc[i][j] = 0.f;

    for (int k0 = 0; k0 < K; k0 += 16) {
        int gr = block_row + a_r;
        float4 v0 = make_float4(0.f, 0.f, 0.f, 0.f);
        float4 v1 = make_float4(0.f, 0.f, 0.f, 0.f);
        if (gr < M) {
            const float* ap = A + (size_t)gr * K + k0 + a_k;
            v0 = *(const float4*)ap;
            v1 = *(const float4*)(ap + 4);
        }
        As[a_k + 0][a_r] = v0.x; As[a_k + 1][a_r] = v0.y;
        As[a_k + 2][a_r] = v0.z; As[a_k + 3][a_r] = v0.w;
        As[a_k + 4][a_r] = v1.x; As[a_k + 5][a_r] = v1.y;
        As[a_k + 6][a_r] = v1.z; As[a_k + 7][a_r] = v1.w;
        const float* bp = W + (size_t)(k0 + b_k) * 128 + b_c;
        *(float4*)&Bs[b_k][b_c]     = *(const float4*)bp;
        *(float4*)&Bs[b_k][b_c + 4] = *(const float4*)(bp + 4);
        __syncthreads();

#pragma unroll
        for (int kk = 0; kk < 16; kk++) {
            float4 a0 = *(const float4*)&As[kk][trow];
            float4 a1 = *(const float4*)&As[kk][trow + 4];
            float4 b0 = *(const float4*)&Bs[kk][tcol];
            float4 b1 = *(const float4*)&Bs[kk][tcol + 4];
            float a[8] = {a0.x, a0.y, a0.z, a0.w, a1.x, a1.y, a1.z, a1.w};
            float b[8] = {b0.x, b0.y, b0.z, b0.w, b1.x, b1.y, b1.z, b1.w};
#pragma unroll
            for (int i = 0; i < 8; i++)
#pragma unroll
                for (int j = 0; j < 8; j++)
                    acc[i][j] = fmaf(a[i], b[j], acc[i][j]);
        }
        __syncthreads();
    }

#pragma unroll
    for (int i = 0; i < 8; i++) {
        int gr = block_row + trow + i;
        if (gr < M) {
            float s = g_dis[gr];
            float4 o0, o1;
            o0.x = acc[i][0] * s; o0.y = acc[i][1] * s;
            o0.z = acc[i][2] * s; o0.w = acc[i][3] * s;
            o1.x = acc[i][4] * s; o1.y = acc[i][5] * s;
            o1.z = acc[i][6] * s; o1.w = acc[i][7] * s;
            float* cp = C + (size_t)gr * 128 + tcol;
            *(float4*)cp = o0;
            *(float4*)(cp + 4) = o1;
        }
    }
}

// ---------------- aggregation: out[i] = act(dis[i]*(hs[i] + sum hs[src]) + bias) ----
// reads g_h; writes outExt if non-null, else g_x1 (layer 1, with relu).
// one warp per node, float4 per lane (32 lanes * 4 floats = 128 cols)
__global__ void __launch_bounds__(256)
agg_kernel(const float* __restrict__ bias, float* __restrict__ outExt,
           int N, int doRelu) {
    const float* hs = (const float*)g_h;
    float* out = outExt ? outExt : (float*)g_x1;

    int w = (blockIdx.x * blockDim.x + threadIdx.x) >> 5;
    int lane = threadIdx.x & 31;
    if (w >= N) return;

    float4 acc = *((const float4*)(hs + (size_t)w * DH) + lane);  // self loop
    int s0 = g_rowptr[w], s1 = g_rowptr[w + 1];
    for (int e0 = s0; e0 < s1; e0 += 32) {
        int cnt = min(32, s1 - e0);
        int sidx = 0;
        if (lane < cnt) sidx = g_esrc[e0 + lane];
        for (int j = 0; j < cnt; j++) {
            int s = __shfl_sync(0xffffffffu, sidx, j);
            float4 v = *((const float4*)(hs + (size_t)s * DH) + lane);
            acc.x += v.x; acc.y += v.y; acc.z += v.z; acc.w += v.w;
        }
    }
    float d = g_dis[w];
    float4 b = *((const float4*)bias + lane);
    float4 r;
    r.x = fmaf(d, acc.x, b.x);
    r.y = fmaf(d, acc.y, b.y);
    r.z = fmaf(d, acc.z, b.z);
    r.w = fmaf(d, acc.w, b.w);
    if (doRelu) {
        r.x = fmaxf(r.x, 0.f); r.y = fmaxf(r.y, 0.f);
        r.z = fmaxf(r.z, 0.f); r.w = fmaxf(r.w, 0.f);
    }
    *((float4*)(out + (size_t)w * DH) + lane) = r;
}

// ---------------- launch ----------------
extern "C" void kernel_launch(void* const* d_in, const int* in_sizes, int n_in,
                              void* d_out, int out_size) {
    const float* x  = (const float*)d_in[0];      // [N, 256]
    const void*  ei = d_in[1];                    // [2, E] int64 OR int32
    const float* W1 = (const float*)d_in[2];      // [256, 128]
    const float* b1 = (const float*)d_in[3];      // [128]
    const float* W2 = (const float*)d_in[4];      // [128, 128]
    const float* b2 = (const float*)d_in[5];      // [128]
    float* out = (float*)d_out;

    int N = in_sizes[0] / 256;
    int E = in_sizes[1] / 2;

    // graph preprocessing (dtype detect + CSR by dst + symmetric norm)
    detect_kernel<<<1, 256>>>((const int*)ei, E);
    zero_kernel<<<(N + 255) / 256, 256>>>(N);
    hist_kernel<<<512, 256>>>(ei, E);
    dis_kernel<<<(N + 255) / 256, 256>>>(N);
    scan_kernel<<<1, 1024>>>(N);
    scatter_kernel<<<512, 256>>>(ei, E);

    // layer 1: g_h = dis*(x@W1); g_x1 = relu(dis*(gather-sum)+b1)
    gemm128<<<(N + 127) / 128, 256>>>(x, W1, N, 256);
    agg_kernel<<<(N + 7) / 8, 256>>>(b1, nullptr, N, 1);

    // layer 2: g_h = dis*(x1@W2); out = dis*(gather-sum)+b2
    gemm128<<<(N + 127) / 128, 256>>>(nullptr, W2, N, 128);
    agg_kernel<<<(N + 7) / 8, 256>>>(b2, out, N, 0);
}

// round 11
// speedup vs baseline: 1.1975x; 1.1975x over previous
#include <cuda_runtime.h>
#include <cuda_bf16.h>
#include <stdint.h>

#define MAXN 50000
#define MAXE 800000
#define DH 128

// ---------------- device scratch (no allocs allowed; 16B-aligned) ----------------
__device__ __align__(16) int   g_hist[MAXN];
__device__ __align__(16) int   g_cnt[MAXN];
__device__ __align__(16) int   g_rowptr[MAXN + 1];
__device__ __align__(16) int   g_esrc[MAXE];
__device__ __align__(16) float g_dis[MAXN];
__device__ __align__(16) float g_h[(size_t)MAXN * DH];   // hs (per layer, reused)
__device__ __align__(16) float g_x1[(size_t)MAXN * DH];  // relu output of layer 1
__device__ int g_is64;
// bf16 hi/lo chunk images of W1/W2. Chunk = 32 K-rows; each row 272 B
// (128 bf16 = 256 B data + 16 B pad so ldmatrix rows land in distinct banksets).
// Per chunk: hi (32*272=8704 B) then lo (8704 B) = 17408 B.
// Layer1: chunks 0..7 (K=256); layer2: chunks 8..11 (K=128).
#define BCHUNK_BYTES 17408
#define B_ROW_STRIDE 272
__device__ __align__(16) unsigned char g_bimg[12 * BCHUNK_BYTES];

// A tile strides in gemm SMEM: 32 K bf16 = 64 B data + 16 B pad = 80 B
#define A_ROW_STRIDE 80

// ---------------- ptx helpers (all PTX here is sm_80-era, compute_103-safe) ------
__device__ __forceinline__ uint32_t smem_u32(const void* p) {
    uint32_t a;
    asm("{ .reg .u64 t; cvta.to.shared.u64 t, %1; cvt.u32.u64 %0, t; }" : "=r"(a) : "l"(p));
    return a;
}
__device__ __forceinline__ void ldsm4(uint32_t* r, uint32_t addr) {
    asm volatile("ldmatrix.sync.aligned.m8n8.x4.shared.b16 {%0,%1,%2,%3}, [%4];"
                 : "=r"(r[0]), "=r"(r[1]), "=r"(r[2]), "=r"(r[3]) : "r"(addr));
}
__device__ __forceinline__ void ldsm4t(uint32_t* r, uint32_t addr) {
    asm volatile("ldmatrix.sync.aligned.m8n8.x4.trans.shared.b16 {%0,%1,%2,%3}, [%4];"
                 : "=r"(r[0]), "=r"(r[1]), "=r"(r[2]), "=r"(r[3]) : "r"(addr));
}
__device__ __forceinline__ void mma_bf16(float* d, const uint32_t* a, const uint32_t* b) {
    asm volatile(
        "mma.sync.aligned.m16n8k16.row.col.f32.bf16.bf16.f32 "
        "{%0,%1,%2,%3}, {%4,%5,%6,%7}, {%8,%9}, {%0,%1,%2,%3};"
        : "+f"(d[0]), "+f"(d[1]), "+f"(d[2]), "+f"(d[3])
        : "r"(a[0]), "r"(a[1]), "r"(a[2]), "r"(a[3]), "r"(b[0]), "r"(b[1]));
}

// ---------------- edge dtype detect ----------------
__global__ void detect_kernel(const int* __restrict__ ei32, int E) {
    __shared__ int found;
    if (threadIdx.x == 0) found = 0;
    __syncthreads();
    int lim = min(4096, E);
    int nz = 0;
    for (int i = threadIdx.x; i < lim; i += blockDim.x) nz |= ei32[2 * i + 1];
    if (nz) atomicOr(&found, 1);
    __syncthreads();
    if (threadIdx.x == 0) g_is64 = (found == 0) ? 1 : 0;
}

__device__ __forceinline__ int load_idx(const void* ei, int E, int which, int i) {
    if (g_is64) return (int)((const long long*)ei)[(size_t)which * E + i];
    return ((const int*)ei)[(size_t)which * E + i];
}

// ---------------- graph preprocessing ----------------
__global__ void zero_kernel(int n) {
    int i = blockIdx.x * blockDim.x + threadIdx.x;
    if (i < n) { g_hist[i] = 0; g_cnt[i] = 0; }
}

__global__ void hist_kernel(const void* __restrict__ ei, int E) {
    int i = blockIdx.x * blockDim.x + threadIdx.x;
    int stride = gridDim.x * blockDim.x;
    for (; i < E; i += stride) {
        int d = load_idx(ei, E, 1, i);
        if (d >= 0 && d < MAXN) atomicAdd(&g_hist[d], 1);
    }
}

__global__ void dis_kernel(int n) {
    int i = blockIdx.x * blockDim.x + threadIdx.x;
    if (i < n) g_dis[i] = rsqrtf((float)(g_hist[i] + 1));
}

__global__ void scan_kernel(int n) {
    __shared__ int sums[1024];
    int tid = threadIdx.x;
    int chunk = (n + 1023) >> 10;
    int b = tid * chunk;
    int e = min(b + chunk, n);
    int s = 0;
    for (int i = b; i < e; i++) s += g_hist[i];
    sums[tid] = s;
    __syncthreads();
    for (int off = 1; off < 1024; off <<= 1) {
        int v = (tid >= off) ? sums[tid - off] : 0;
        __syncthreads();
        sums[tid] += v;
        __syncthreads();
    }
    int run = (tid > 0) ? sums[tid - 1] : 0;
    for (int i = b; i < e; i++) { g_rowptr[i] = run; run += g_hist[i]; }
    if (b < n && e == n) g_rowptr[n] = run;
}

__global__ void scatter_kernel(const void* __restrict__ ei, int E) {
    int i = blockIdx.x * blockDim.x + threadIdx.x;
    int stride = gridDim.x * blockDim.x;
    for (; i < E; i += stride) {
        int d = load_idx(ei, E, 1, i);
        if (d < 0 || d >= MAXN) continue;
        int pos = g_rowptr[d] + atomicAdd(&g_cnt[d], 1);
        int s = load_idx(ei, E, 0, i);
        if (pos >= 0 && pos < MAXE) g_esrc[pos] = s;
    }
}

// ---------------- W -> bf16 hi/lo chunk images (plain layout, padded rows) -------
__global__ void convB_kernel(const float* __restrict__ W, int K, int chunkBase) {
    int idx = blockIdx.x * blockDim.x + threadIdx.x;
    if (idx >= K * 128) return;
    int n = idx & 127;
    int k = idx >> 7;
    float v = W[(size_t)k * 128 + n];
    __nv_bfloat16 hb = __float2bfloat16(v);
    float lo = v - __bfloat162float(hb);
    __nv_bfloat16 lb = __float2bfloat16(lo);
    int c = k >> 5;
    int kl = k & 31;
    size_t base = (size_t)(chunkBase + c) * BCHUNK_BYTES + (size_t)kl * B_ROW_STRIDE + n * 2;
    *(unsigned short*)(g_bimg + base) = __bfloat16_as_ushort(hb);
    *(unsigned short*)(g_bimg + base + 8704) = __bfloat16_as_ushort(lb);
}

// ---------------- tensor-core GEMM via mma.sync: g_h = dis * (A @ W) -------------
// Split bf16: A@W ~= Ahi@Whi + Ahi@Wlo + Alo@Whi; fp32 register accumulators.
// CTA tile 128x128, 8 warps of 32x64; K in chunks of 32 (2 k16 steps).
__global__ void __launch_bounds__(256)
gemm_mma(const float* __restrict__ Aext, int M, int K, int chunkBase) {
    __shared__ __align__(16) unsigned char As[2][128 * A_ROW_STRIDE];  // hi, lo
    __shared__ __align__(16) unsigned char Bs[2][32 * B_ROW_STRIDE];   // hi, lo

    const float* A = Aext ? Aext : (const float*)g_x1;
    float* C = (float*)g_h;

    const int tid = threadIdx.x;
    const int wid = tid >> 5;
    const int lane = tid & 31;
    const int block_row = blockIdx.x * 128;
    const int mr = (wid & 3) * 32;   // warp row offset in tile
    const int nc = (wid >> 2) * 64;  // warp col offset

    const uint32_t as_base = smem_u32(&As[0][0]);
    const uint32_t bs_base = smem_u32(&Bs[0][0]);

    // ldmatrix lane-address components
    const int a_lrow = lane & 15;
    const int a_lk16 = (lane >> 4) * 16;           // byte offset within k-step
    const int b_lk = (lane & 7) | (((lane >> 3) & 1) << 3);
    const int b_ln8 = (lane >> 4) * 8;

    float d[2][8][4];
#pragma unroll
    for (int mi = 0; mi < 2; mi++)
#pragma unroll
        for (int j = 0; j < 8; j++)
#pragma unroll
            for (int q = 0; q < 4; q++) d[mi][j][q] = 0.f;

    const int nchunks = K >> 5;
    for (int c = 0; c < nchunks; c++) {
        // ---- fill A chunk: 128 rows x 32 k, fp32 -> bf16 hi/lo ----
#pragma unroll
        for (int i = 0; i < 2; i++) {
            int idx = tid + i * 256;          // 0..511
            int row = idx >> 2;               // 0..127
            int kl = (idx & 3) << 3;          // 0,8,16,24
            int gr = block_row + row;
            float v[8];
#pragma unroll
            for (int j = 0; j < 8; j++) v[j] = 0.f;
            if (gr < M) {
                const float* ap = A + (size_t)gr * K + (c << 5) + kl;
                float4 a0 = *(const float4*)ap;
                float4 a1 = *(const float4*)(ap + 4);
                v[0] = a0.x; v[1] = a0.y; v[2] = a0.z; v[3] = a0.w;
                v[4] = a1.x; v[5] = a1.y; v[6] = a1.z; v[7] = a1.w;
            }
            unsigned short h[8], l[8];
#pragma unroll
            for (int j = 0; j < 8; j++) {
                __nv_bfloat16 hb = __float2bfloat16(v[j]);
                float r = v[j] - __bfloat162float(hb);
                h[j] = __bfloat16_as_ushort(hb);
                l[j] = __bfloat16_as_ushort(__float2bfloat16(r));
            }
            uint4 uh, ul;
            uh.x = (uint32_t)h[0] | ((uint32_t)h[1] << 16);
            uh.y = (uint32_t)h[2] | ((uint32_t)h[3] << 16);
            uh.z = (uint32_t)h[4] | ((uint32_t)h[5] << 16);
            uh.w = (uint32_t)h[6] | ((uint32_t)h[7] << 16);
            ul.x = (uint32_t)l[0] | ((uint32_t)l[1] << 16);
            ul.y = (uint32_t)l[2] | ((uint32_t)l[3] << 16);
            ul.z = (uint32_t)l[4] | ((uint32_t)l[5] << 16);
            ul.w = (uint32_t)l[6] | ((uint32_t)l[7] << 16);
            uint32_t off = (uint32_t)row * A_ROW_STRIDE + (uint32_t)kl * 2;
            *(uint4*)(&As[0][off]) = uh;
            *(uint4*)(&As[1][off]) = ul;
        }
        // ---- copy B chunk (hi+lo = 17408 B) from image ----
        {
            const uint4* src = (const uint4*)(g_bimg + (size_t)(chunkBase + c) * BCHUNK_BYTES);
            uint4* dst = (uint4*)&Bs[0][0];
            for (int j = tid; j < BCHUNK_BYTES / 16; j += 256) dst[j] = src[j];
        }
        __syncthreads();

        // ---- 2 k16 steps ----
#pragma unroll
        for (int s = 0; s < 2; s++) {
            uint32_t ah[2][4], al[2][4];
#pragma unroll
            for (int mi = 0; mi < 2; mi++) {
                uint32_t arow = (uint32_t)(mr + mi * 16 + a_lrow) * A_ROW_STRIDE
                              + (uint32_t)s * 32 + a_lk16;
                ldsm4(ah[mi], as_base + arow);
                ldsm4(al[mi], as_base + 128 * A_ROW_STRIDE + arow);
            }
#pragma unroll
            for (int t = 0; t < 4; t++) {
                uint32_t boff = (uint32_t)(s * 16 + b_lk) * B_ROW_STRIDE
                              + (uint32_t)(nc + t * 16 + b_ln8) * 2;
                uint32_t bh[4], bl[4];
                ldsm4t(bh, bs_base + boff);
                ldsm4t(bl, bs_base + 32 * B_ROW_STRIDE + boff);
#pragma unroll
                for (int mi = 0; mi < 2; mi++) {
                    mma_bf16(d[mi][2 * t],     ah[mi], bh);       // hi*hi
                    mma_bf16(d[mi][2 * t + 1], ah[mi], bh + 2);
                    mma_bf16(d[mi][2 * t],     ah[mi], bl);       // hi*lo
                    mma_bf16(d[mi][2 * t + 1], ah[mi], bl + 2);
                    mma_bf16(d[mi][2 * t],     al[mi], bh);       // lo*hi
                    mma_bf16(d[mi][2 * t + 1], al[mi], bh + 2);
                }
            }
        }
        __syncthreads();
    }

    // ---- epilogue: scale by dis[row], store fp32 ----
#pragma unroll
    for (int mi = 0; mi < 2; mi++) {
        int r0 = block_row + mr + mi * 16 + (lane >> 2);
        int r1 = r0 + 8;
        float s0 = (r0 < M) ? g_dis[r0] : 0.f;
        float s1 = (r1 < M) ? g_dis[r1] : 0.f;
#pragma unroll
        for (int j = 0; j < 8; j++) {
            int col = nc + j * 8 + (lane & 3) * 2;
            if (r0 < M) {
                float2 v = make_float2(d[mi][j][0] * s0, d[mi][j][1] * s0);
                *(float2*)(C + (size_t)r0 * 128 + col) = v;
            }
            if (r1 < M) {
                float2 v = make_float2(d[mi][j][2] * s1, d[mi][j][3] * s1);
                *(float2*)(C + (size_t)r1 * 128 + col) = v;
            }
        }
    }
}

// ---------------- aggregation: out[i] = act(dis[i]*(hs[i] + sum hs[src]) + bias) ----
__global__ void __launch_bounds__(256)
agg_kernel(const float* __restrict__ bias, float* __restrict__ outExt,
           int N, int doRelu) {
    const float* hs = (const float*)g_h;
    float* out = outExt ? outExt : (float*)g_x1;

    int w = (blockIdx.x * blockDim.x + threadIdx.x) >> 5;
    int lane = threadIdx.x & 31;
    if (w >= N) return;

    float4 acc = *((const float4*)(hs + (size_t)w * DH) + lane);  // self loop
    int s0 = g_rowptr[w], s1 = g_rowptr[w + 1];
    for (int e0 = s0; e0 < s1; e0 += 32) {
        int cnt = min(32, s1 - e0);
        int sidx = 0;
        if (lane < cnt) sidx = g_esrc[e0 + lane];
        for (int j = 0; j < cnt; j++) {
            int s = __shfl_sync(0xffffffffu, sidx, j);
            float4 v = *((const float4*)(hs + (size_t)s * DH) + lane);
            acc.x += v.x; acc.y += v.y; acc.z += v.z; acc.w += v.w;
        }
    }
    float d = g_dis[w];
    float4 b = *((const float4*)bias + lane);
    float4 r;
    r.x = fmaf(d, acc.x, b.x);
    r.y = fmaf(d, acc.y, b.y);
    r.z = fmaf(d, acc.z, b.z);
    r.w = fmaf(d, acc.w, b.w);
    if (doRelu) {
        r.x = fmaxf(r.x, 0.f); r.y = fmaxf(r.y, 0.f);
        r.z = fmaxf(r.z, 0.f); r.w = fmaxf(r.w, 0.f);
    }
    *((float4*)(out + (size_t)w * DH) + lane) = r;
}

// ---------------- launch ----------------
extern "C" void kernel_launch(void* const* d_in, const int* in_sizes, int n_in,
                              void* d_out, int out_size) {
    const float* x  = (const float*)d_in[0];      // [N, 256]
    const void*  ei = d_in[1];                    // [2, E] int64 OR int32
    const float* W1 = (const float*)d_in[2];      // [256, 128]
    const float* b1 = (const float*)d_in[3];      // [128]
    const float* W2 = (const float*)d_in[4];      // [128, 128]
    const float* b2 = (const float*)d_in[5];      // [128]
    float* out = (float*)d_out;

    int N = in_sizes[0] / 256;
    int E = in_sizes[1] / 2;

    // graph preprocessing (dtype detect + CSR by dst + symmetric norm)
    detect_kernel<<<1, 256>>>((const int*)ei, E);
    zero_kernel<<<(N + 255) / 256, 256>>>(N);
    hist_kernel<<<512, 256>>>(ei, E);
    dis_kernel<<<(N + 255) / 256, 256>>>(N);
    scan_kernel<<<1, 1024>>>(N);
    scatter_kernel<<<512, 256>>>(ei, E);

    // weight preconversion to bf16 hi/lo chunk images
    convB_kernel<<<(256 * 128 + 255) / 256, 256>>>(W1, 256, 0);
    convB_kernel<<<(128 * 128 + 255) / 256, 256>>>(W2, 128, 8);

    int gblocks = (N + 127) / 128;
    // layer 1: g_h = dis*(x@W1); g_x1 = relu(dis*(gather-sum)+b1)
    gemm_mma<<<gblocks, 256>>>(x, N, 256, 0);
    agg_kernel<<<(N + 7) / 8, 256>>>(b1, nullptr, N, 1);

    // layer 2: g_h = dis*(x1@W2); out = dis*(gather-sum)+b2
    gemm_mma<<<gblocks, 256>>>(nullptr, N, 128, 8);
    agg_kernel<<<(N + 7) / 8, 256>>>(b2, out, N, 0);
}

// round 16
// speedup vs baseline: 1.2153x; 1.0149x over previous
#include <cuda_runtime.h>
#include <cuda_bf16.h>
#include <stdint.h>

#define MAXN 50000
#define MAXE 800000
#define DH 128

// ---------------- device scratch (no allocs allowed; 16B-aligned) ----------------
__device__ __align__(16) int   g_hist[MAXN];
__device__ __align__(16) int   g_cnt[MAXN];
__device__ __align__(16) int   g_rowptr[MAXN + 1];
__device__ __align__(16) int   g_esrc[MAXE];
__device__ __align__(16) float g_dis[MAXN];
__device__ __align__(16) float g_h[(size_t)MAXN * DH];   // hs (per layer, reused)
__device__ __align__(16) float g_x1[(size_t)MAXN * DH];  // relu output of layer 1
__device__ int g_is64;
// bf16 hi/lo chunk images of W1/W2. Chunk = 32 K-rows; row = 272 B
// (128 bf16 = 256 B + 16 B pad -> ldmatrix rows hit distinct banksets).
// Per chunk: hi (8704 B) then lo (8704 B). L1: chunks 0..7; L2: chunks 8..11.
#define BCHUNK_BYTES 17408
#define B_ROW_STRIDE 272
__device__ __align__(16) unsigned char g_bimg[12 * BCHUNK_BYTES];

#define A_ROW_STRIDE 80   // 32 K bf16 = 64 B + 16 B pad

// ---------------- ptx helpers (sm_80-era, compute_103-safe) ------
__device__ __forceinline__ uint32_t smem_u32(const void* p) {
    uint32_t a;
    asm("{ .reg .u64 t; cvta.to.shared.u64 t, %1; cvt.u32.u64 %0, t; }" : "=r"(a) : "l"(p));
    return a;
}
__device__ __forceinline__ void ldsm4(uint32_t* r, uint32_t addr) {
    asm volatile("ldmatrix.sync.aligned.m8n8.x4.shared.b16 {%0,%1,%2,%3}, [%4];"
                 : "=r"(r[0]), "=r"(r[1]), "=r"(r[2]), "=r"(r[3]) : "r"(addr));
}
__device__ __forceinline__ void ldsm4t(uint32_t* r, uint32_t addr) {
    asm volatile("ldmatrix.sync.aligned.m8n8.x4.trans.shared.b16 {%0,%1,%2,%3}, [%4];"
                 : "=r"(r[0]), "=r"(r[1]), "=r"(r[2]), "=r"(r[3]) : "r"(addr));
}
__device__ __forceinline__ void mma_bf16(float* d, const uint32_t* a, const uint32_t* b) {
    asm volatile(
        "mma.sync.aligned.m16n8k16.row.col.f32.bf16.bf16.f32 "
        "{%0,%1,%2,%3}, {%4,%5,%6,%7}, {%8,%9}, {%0,%1,%2,%3};"
        : "+f"(d[0]), "+f"(d[1]), "+f"(d[2]), "+f"(d[3])
        : "r"(a[0]), "r"(a[1]), "r"(a[2]), "r"(a[3]), "r"(b[0]), "r"(b[1]));
}
__device__ __forceinline__ void cp16(uint32_t saddr, const void* g) {
    asm volatile("cp.async.cg.shared.global [%0], [%1], 16;" :: "r"(saddr), "l"(g));
}
__device__ __forceinline__ void cp_commit() {
    asm volatile("cp.async.commit_group;" ::: "memory");
}
__device__ __forceinline__ void cp_wait0() {
    asm volatile("cp.async.wait_group 0;" ::: "memory");
}

// ---------------- init: zero hist/cnt + edge dtype detect (block 0) --------------
__global__ void init_kernel(const int* __restrict__ ei32, int E, int n) {
    int i = blockIdx.x * blockDim.x + threadIdx.x;
    if (i < n) { g_hist[i] = 0; g_cnt[i] = 0; }
    if (blockIdx.x == 0) {
        __shared__ int found;
        if (threadIdx.x == 0) found = 0;
        __syncthreads();
        int lim = min(4096, E);
        int nz = 0;
        for (int k = threadIdx.x; k < lim; k += blockDim.x) nz |= ei32[2 * k + 1];
        if (nz) atomicOr(&found, 1);
        __syncthreads();
        if (threadIdx.x == 0) g_is64 = (found == 0) ? 1 : 0;
    }
}

__device__ __forceinline__ int load_idx(const void* ei, int E, int which, int i) {
    if (g_is64) return (int)((const long long*)ei)[(size_t)which * E + i];
    return ((const int*)ei)[(size_t)which * E + i];
}

// ---------------- graph preprocessing ----------------
__global__ void hist_kernel(const void* __restrict__ ei, int E) {
    int i = blockIdx.x * blockDim.x + threadIdx.x;
    int stride = gridDim.x * blockDim.x;
    for (; i < E; i += stride) {
        int d = load_idx(ei, E, 1, i);
        if (d >= 0 && d < MAXN) atomicAdd(&g_hist[d], 1);
    }
}

// single-block scan + dis computation
__global__ void scan_kernel(int n) {
    __shared__ int sums[1024];
    int tid = threadIdx.x;
    int chunk = (n + 1023) >> 10;
    int b = tid * chunk;
    int e = min(b + chunk, n);
    int s = 0;
    for (int i = b; i < e; i++) {
        int h = g_hist[i];
        s += h;
        g_dis[i] = rsqrtf((float)(h + 1));
    }
    sums[tid] = s;
    __syncthreads();
    for (int off = 1; off < 1024; off <<= 1) {
        int v = (tid >= off) ? sums[tid - off] : 0;
        __syncthreads();
        sums[tid] += v;
        __syncthreads();
    }
    int run = (tid > 0) ? sums[tid - 1] : 0;
    for (int i = b; i < e; i++) { g_rowptr[i] = run; run += g_hist[i]; }
    if (b < n && e == n) g_rowptr[n] = run;
}

__global__ void scatter_kernel(const void* __restrict__ ei, int E) {
    int i = blockIdx.x * blockDim.x + threadIdx.x;
    int stride = gridDim.x * blockDim.x;
    for (; i < E; i += stride) {
        int d = load_idx(ei, E, 1, i);
        if (d < 0 || d >= MAXN) continue;
        int pos = g_rowptr[d] + atomicAdd(&g_cnt[d], 1);
        int s = load_idx(ei, E, 0, i);
        if (pos >= 0 && pos < MAXE) g_esrc[pos] = s;
    }
}

// ---------------- W1+W2 -> bf16 hi/lo chunk images -------------------------------
__global__ void convB_kernel(const float* __restrict__ W1, const float* __restrict__ W2) {
    int idx = blockIdx.x * blockDim.x + threadIdx.x;
    const float* W;
    int chunkBase;
    if (idx < 256 * 128) { W = W1; chunkBase = 0; }
    else if (idx < 256 * 128 + 128 * 128) { W = W2; chunkBase = 8; idx -= 256 * 128; }
    else return;
    int n = idx & 127;
    int k = idx >> 7;
    float v = W[(size_t)k * 128 + n];
    __nv_bfloat16 hb = __float2bfloat16(v);
    float lo = v - __bfloat162float(hb);
    __nv_bfloat16 lb = __float2bfloat16(lo);
    int c = k >> 5;
    int kl = k & 31;
    size_t base = (size_t)(chunkBase + c) * BCHUNK_BYTES + (size_t)kl * B_ROW_STRIDE + n * 2;
    *(unsigned short*)(g_bimg + base) = __bfloat16_as_ushort(hb);
    *(unsigned short*)(g_bimg + base + 8704) = __bfloat16_as_ushort(lb);
}

// ---------------- tensor-core GEMM via mma.sync: g_h = dis * (A @ W) -------------
// Split bf16: A@W ~= Ahi@Whi + Ahi@Wlo + Alo@Whi; fp32 register accumulators.
// CTA tile 128x128, 8 warps of 32x64; K in chunks of 32 (2 k16 steps).
// Pipelined: B via cp.async; A(c+1) prefetched to regs before MMA(c).
__global__ void __launch_bounds__(256)
gemm_mma(const float* __restrict__ Aext, int M, int K, int chunkBase) {
    __shared__ __align__(16) unsigned char As[2][128 * A_ROW_STRIDE];  // hi, lo
    __shared__ __align__(16) unsigned char Bs[2][32 * B_ROW_STRIDE];   // hi, lo (flat 17408 B)

    const float* A = Aext ? Aext : (const float*)g_x1;
    float* C = (float*)g_h;

    const int tid = threadIdx.x;
    const int wid = tid >> 5;
    const int lane = tid & 31;
    const int block_row = blockIdx.x * 128;
    const int mr = (wid & 3) * 32;
    const int nc = (wid >> 2) * 64;

    const uint32_t as_base = smem_u32(&As[0][0]);
    const uint32_t bs_base = smem_u32(&Bs[0][0]);

    const int a_lrow = lane & 15;
    const int a_lk16 = (lane >> 4) * 16;
    const int b_lk = (lane & 7) | (((lane >> 3) & 1) << 3);
    const int b_ln8 = (lane >> 4) * 8;

    // per-thread A fill coordinates (2 items of 8 floats)
    const int f_row0 = tid >> 2;               // 0..63
    const int f_row1 = (tid + 256) >> 2;       // 64..127
    const int f_kl = (tid & 3) << 3;           // 0,8,16,24

    float d[2][8][4];
#pragma unroll
    for (int mi = 0; mi < 2; mi++)
#pragma unroll
        for (int j = 0; j < 8; j++)
#pragma unroll
            for (int q = 0; q < 4; q++) d[mi][j][q] = 0.f;

    const int nchunks = K >> 5;
    float pv[2][8];

    // prefetch A chunk 0
#pragma unroll
    for (int i = 0; i < 2; i++) {
        int row = i ? f_row1 : f_row0;
        int gr = block_row + row;
#pragma unroll
        for (int j = 0; j < 8; j++) pv[i][j] = 0.f;
        if (gr < M) {
            const float* ap = A + (size_t)gr * K + f_kl;
            float4 a0 = *(const float4*)ap;
            float4 a1 = *(const float4*)(ap + 4);
            pv[i][0] = a0.x; pv[i][1] = a0.y; pv[i][2] = a0.z; pv[i][3] = a0.w;
            pv[i][4] = a1.x; pv[i][5] = a1.y; pv[i][6] = a1.z; pv[i][7] = a1.w;
        }
    }

    for (int c = 0; c < nchunks; c++) {
        // ---- kick off B chunk copy via cp.async (1088 x 16 B) ----
        {
            const uint4* src = (const uint4*)(g_bimg + (size_t)(chunkBase + c) * BCHUNK_BYTES);
#pragma unroll
            for (int k = 0; k < 5; k++) {
                int j = tid + k * 256;
                if (j < BCHUNK_BYTES / 16) cp16(bs_base + j * 16, src + j);
            }
            cp_commit();
        }
        // ---- convert prefetched A regs -> smem hi/lo ----
#pragma unroll
        for (int i = 0; i < 2; i++) {
            int row = i ? f_row1 : f_row0;
            unsigned short h[8], l[8];
#pragma unroll
            for (int j = 0; j < 8; j++) {
                __nv_bfloat16 hb = __float2bfloat16(pv[i][j]);
                float r = pv[i][j] - __bfloat162float(hb);
                h[j] = __bfloat16_as_ushort(hb);
                l[j] = __bfloat16_as_ushort(__float2bfloat16(r));
            }
            uint4 uh, ul;
            uh.x = (uint32_t)h[0] | ((uint32_t)h[1] << 16);
            uh.y = (uint32_t)h[2] | ((uint32_t)h[3] << 16);
            uh.z = (uint32_t)h[4] | ((uint32_t)h[5] << 16);
            uh.w = (uint32_t)h[6] | ((uint32_t)h[7] << 16);
            ul.x = (uint32_t)l[0] | ((uint32_t)l[1] << 16);
            ul.y = (uint32_t)l[2] | ((uint32_t)l[3] << 16);
            ul.z = (uint32_t)l[4] | ((uint32_t)l[5] << 16);
            ul.w = (uint32_t)l[6] | ((uint32_t)l[7] << 16);
            uint32_t off = (uint32_t)row * A_ROW_STRIDE + (uint32_t)f_kl * 2;
            *(uint4*)(&As[0][off]) = uh;
            *(uint4*)(&As[1][off]) = ul;
        }
        // ---- prefetch A chunk c+1 into regs (overlaps with MMA below) ----
        if (c + 1 < nchunks) {
#pragma unroll
            for (int i = 0; i < 2; i++) {
                int row = i ? f_row1 : f_row0;
                int gr = block_row + row;
#pragma unroll
                for (int j = 0; j < 8; j++) pv[i][j] = 0.f;
                if (gr < M) {
                    const float* ap = A + (size_t)gr * K + ((c + 1) << 5) + f_kl;
                    float4 a0 = *(const float4*)ap;
                    float4 a1 = *(const float4*)(ap + 4);
                    pv[i][0] = a0.x; pv[i][1] = a0.y; pv[i][2] = a0.z; pv[i][3] = a0.w;
                    pv[i][4] = a1.x; pv[i][5] = a1.y; pv[i][6] = a1.z; pv[i][7] = a1.w;
                }
            }
        }
        cp_wait0();
        __syncthreads();

        // ---- 2 k16 steps x 3 split terms ----
#pragma unroll
        for (int s = 0; s < 2; s++) {
            uint32_t ah[2][4], al[2][4];
#pragma unroll
            for (int mi = 0; mi < 2; mi++) {
                uint32_t arow = (uint32_t)(mr + mi * 16 + a_lrow) * A_ROW_STRIDE
                              + (uint32_t)s * 32 + a_lk16;
                ldsm4(ah[mi], as_base + arow);
                ldsm4(al[mi], as_base + 128 * A_ROW_STRIDE + arow);
            }
#pragma unroll
            for (int t = 0; t < 4; t++) {
                uint32_t boff = (uint32_t)(s * 16 + b_lk) * B_ROW_STRIDE
                              + (uint32_t)(nc + t * 16 + b_ln8) * 2;
                uint32_t bh[4], bl[4];
                ldsm4t(bh, bs_base + boff);
                ldsm4t(bl, bs_base + 32 * B_ROW_STRIDE + boff);
#pragma unroll
                for (int mi = 0; mi < 2; mi++) {
                    mma_bf16(d[mi][2 * t],     ah[mi], bh);       // hi*hi
                    mma_bf16(d[mi][2 * t + 1], ah[mi], bh + 2);
                    mma_bf16(d[mi][2 * t],     ah[mi], bl);       // hi*lo
                    mma_bf16(d[mi][2 * t + 1], ah[mi], bl + 2);
                    mma_bf16(d[mi][2 * t],     al[mi], bh);       // lo*hi
                    mma_bf16(d[mi][2 * t + 1], al[mi], bh + 2);
                }
            }
        }
        __syncthreads();
    }

    // ---- epilogue: scale by dis[row], store fp32 ----
#pragma unroll
    for (int mi = 0; mi < 2; mi++) {
        int r0 = block_row + mr + mi * 16 + (lane >> 2);
        int r1 = r0 + 8;
        float s0 = (r0 < M) ? g_dis[r0] : 0.f;
        float s1 = (r1 < M) ? g_dis[r1] : 0.f;
#pragma unroll
        for (int j = 0; j < 8; j++) {
            int col = nc + j * 8 + (lane & 3) * 2;
            if (r0 < M) {
                float2 v = make_float2(d[mi][j][0] * s0, d[mi][j][1] * s0);
                *(float2*)(C + (size_t)r0 * 128 + col) = v;
            }
            if (r1 < M) {
                float2 v = make_float2(d[mi][j][2] * s1, d[mi][j][3] * s1);
                *(float2*)(C + (size_t)r1 * 128 + col) = v;
            }
        }
    }
}

// ---------------- aggregation: out[i] = act(dis[i]*(hs[i] + sum hs[src]) + bias) ----
// one warp per node; inner loop unrolled x4 for memory-level parallelism
__global__ void __launch_bounds__(256)
agg_kernel(const float* __restrict__ bias, float* __restrict__ outExt,
           int N, int doRelu) {
    const float* hs = (const float*)g_h;
    float* out = outExt ? outExt : (float*)g_x1;

    int w = (blockIdx.x * blockDim.x + threadIdx.x) >> 5;
    int lane = threadIdx.x & 31;
    if (w >= N) return;

    const float4* hsv = (const float4*)hs;
    float4 acc = hsv[(size_t)w * 32 + lane];  // self loop
    int s0 = g_rowptr[w], s1 = g_rowptr[w + 1];
    for (int e0 = s0; e0 < s1; e0 += 32) {
        int cnt = min(32, s1 - e0);
        int sidx = 0;
        if (lane < cnt) sidx = g_esrc[e0 + lane];
        int j = 0;
        for (; j + 4 <= cnt; j += 4) {
            int i0 = __shfl_sync(0xffffffffu, sidx, j);
            int i1 = __shfl_sync(0xffffffffu, sidx, j + 1);
            int i2 = __shfl_sync(0xffffffffu, sidx, j + 2);
            int i3 = __shfl_sync(0xffffffffu, sidx, j + 3);
            float4 v0 = hsv[(size_t)i0 * 32 + lane];
            float4 v1 = hsv[(size_t)i1 * 32 + lane];
            float4 v2 = hsv[(size_t)i2 * 32 + lane];
            float4 v3 = hsv[(size_t)i3 * 32 + lane];
            acc.x += (v0.x + v1.x) + (v2.x + v3.x);
            acc.y += (v0.y + v1.y) + (v2.y + v3.y);
            acc.z += (v0.z + v1.z) + (v2.z + v3.z);
            acc.w += (v0.w + v1.w) + (v2.w + v3.w);
        }
        for (; j < cnt; j++) {
            int s = __shfl_sync(0xffffffffu, sidx, j);
            float4 v = hsv[(size_t)s * 32 + lane];
            acc.x += v.x; acc.y += v.y; acc.z += v.z; acc.w += v.w;
        }
    }
    float d = g_dis[w];
    float4 b = *((const float4*)bias + lane);
    float4 r;
    r.x = fmaf(d, acc.x, b.x);
    r.y = fmaf(d, acc.y, b.y);
    r.z = fmaf(d, acc.z, b.z);
    r.w = fmaf(d, acc.w, b.w);
    if (doRelu) {
        r.x = fmaxf(r.x, 0.f); r.y = fmaxf(r.y, 0.f);
        r.z = fmaxf(r.z, 0.f); r.w = fmaxf(r.w, 0.f);
    }
    *((float4*)(out + (size_t)w * DH) + lane) = r;
}

// ---------------- launch ----------------
extern "C" void kernel_launch(void* const* d_in, const int* in_sizes, int n_in,
                              void* d_out, int out_size) {
    const float* x  = (const float*)d_in[0];      // [N, 256]
    const void*  ei = d_in[1];                    // [2, E] int64 OR int32
    const float* W1 = (const float*)d_in[2];      // [256, 128]
    const float* b1 = (const float*)d_in[3];      // [128]
    const float* W2 = (const float*)d_in[4];      // [128, 128]
    const float* b2 = (const float*)d_in[5];      // [128]
    float* out = (float*)d_out;

    int N = in_sizes[0] / 256;
    int E = in_sizes[1] / 2;

    // graph preprocessing (zero+detect, histogram, scan+dis, CSR scatter)
    init_kernel<<<(N + 255) / 256, 256>>>((const int*)ei, E, N);
    hist_kernel<<<512, 256>>>(ei, E);
    scan_kernel<<<1, 1024>>>(N);
    scatter_kernel<<<512, 256>>>(ei, E);

    // weight preconversion to bf16 hi/lo chunk images (both layers, one kernel)
    convB_kernel<<<(256 * 128 + 128 * 128 + 255) / 256, 256>>>(W1, W2);

    int gblocks = (N + 127) / 128;
    // layer 1: g_h = dis*(x@W1); g_x1 = relu(dis*(gather-sum)+b1)
    gemm_mma<<<gblocks, 256>>>(x, N, 256, 0);
    agg_kernel<<<(N + 7) / 8, 256>>>(b1, nullptr, N, 1);

    // layer 2: g_h = dis*(x1@W2); out = dis*(gather-sum)+b2
    gemm_mma<<<gblocks, 256>>>(nullptr, N, 128, 8);
    agg_kernel<<<(N + 7) / 8, 256>>>(b2, out, N, 0);
}

// round 17
// speedup vs baseline: 1.2297x; 1.0118x over previous
#include <cuda_runtime.h>
#include <cuda_bf16.h>
#include <stdint.h>

#define MAXN 50000
#define MAXE 800000
#define DH 128

// ---------------- device scratch (no allocs allowed; 16B-aligned) ----------------
__device__ __align__(16) int   g_hist[MAXN];
__device__ __align__(16) int   g_cnt[MAXN];
__device__ __align__(16) int   g_rowptr[MAXN + 1];
__device__ __align__(16) int   g_esrc[MAXE];
__device__ __align__(16) float g_dis[MAXN];
__device__ __align__(16) float g_h[(size_t)MAXN * DH];   // hs (per layer, reused)
__device__ __align__(16) float g_x1[(size_t)MAXN * DH];  // relu output of layer 1
__device__ int g_is64;
// bf16 hi/lo chunk images of W1/W2. Chunk = 32 K-rows; row = 272 B
// (128 bf16 = 256 B + 16 B pad -> ldmatrix rows hit distinct banksets).
// Per chunk: hi (8704 B) then lo (8704 B). L1: chunks 0..7; L2: chunks 8..11.
#define BCHUNK_BYTES 17408
#define B_ROW_STRIDE 272
__device__ __align__(16) unsigned char g_bimg[12 * BCHUNK_BYTES];

#define A_ROW_STRIDE 80   // 32 K bf16 = 64 B + 16 B pad

// ---------------- ptx helpers (sm_80-era, compute_103-safe) ------
__device__ __forceinline__ uint32_t smem_u32(const void* p) {
    uint32_t a;
    asm("{ .reg .u64 t; cvta.to.shared.u64 t, %1; cvt.u32.u64 %0, t; }" : "=r"(a) : "l"(p));
    return a;
}
__device__ __forceinline__ void ldsm4(uint32_t* r, uint32_t addr) {
    asm volatile("ldmatrix.sync.aligned.m8n8.x4.shared.b16 {%0,%1,%2,%3}, [%4];"
                 : "=r"(r[0]), "=r"(r[1]), "=r"(r[2]), "=r"(r[3]) : "r"(addr));
}
__device__ __forceinline__ void ldsm4t(uint32_t* r, uint32_t addr) {
    asm volatile("ldmatrix.sync.aligned.m8n8.x4.trans.shared.b16 {%0,%1,%2,%3}, [%4];"
                 : "=r"(r[0]), "=r"(r[1]), "=r"(r[2]), "=r"(r[3]) : "r"(addr));
}
__device__ __forceinline__ void mma_bf16(float* d, const uint32_t* a, const uint32_t* b) {
    asm volatile(
        "mma.sync.aligned.m16n8k16.row.col.f32.bf16.bf16.f32 "
        "{%0,%1,%2,%3}, {%4,%5,%6,%7}, {%8,%9}, {%0,%1,%2,%3};"
        : "+f"(d[0]), "+f"(d[1]), "+f"(d[2]), "+f"(d[3])
        : "r"(a[0]), "r"(a[1]), "r"(a[2]), "r"(a[3]), "r"(b[0]), "r"(b[1]));
}
__device__ __forceinline__ void cp16(uint32_t saddr, const void* g) {
    asm volatile("cp.async.cg.shared.global [%0], [%1], 16;" :: "r"(saddr), "l"(g));
}
__device__ __forceinline__ void cp_commit() {
    asm volatile("cp.async.commit_group;" ::: "memory");
}
__device__ __forceinline__ void cp_wait0() {
    asm volatile("cp.async.wait_group 0;" ::: "memory");
}

// ---------------- init: zero hist/cnt + edge dtype detect (block 0) --------------
__global__ void init_kernel(const int* __restrict__ ei32, int E, int n) {
    int i = blockIdx.x * blockDim.x + threadIdx.x;
    if (i < n) { g_hist[i] = 0; g_cnt[i] = 0; }
    if (blockIdx.x == 0) {
        __shared__ int found;
        if (threadIdx.x == 0) found = 0;
        __syncthreads();
        int lim = min(4096, E);
        int nz = 0;
        for (int k = threadIdx.x; k < lim; k += blockDim.x) nz |= ei32[2 * k + 1];
        if (nz) atomicOr(&found, 1);
        __syncthreads();
        if (threadIdx.x == 0) g_is64 = (found == 0) ? 1 : 0;
    }
}

__device__ __forceinline__ int load_idx(const void* ei, int E, int which, int i) {
    if (g_is64) return (int)((const long long*)ei)[(size_t)which * E + i];
    return ((const int*)ei)[(size_t)which * E + i];
}

// ---------------- graph preprocessing (one edge per thread: latency-hiding) ------
__global__ void hist_kernel(const void* __restrict__ ei, int E) {
    int i = blockIdx.x * blockDim.x + threadIdx.x;
    if (i >= E) return;
    int d = load_idx(ei, E, 1, i);
    if (d >= 0 && d < MAXN) atomicAdd(&g_hist[d], 1);
}

// single-block scan + dis computation
__global__ void scan_kernel(int n) {
    __shared__ int sums[1024];
    int tid = threadIdx.x;
    int chunk = (n + 1023) >> 10;
    int b = tid * chunk;
    int e = min(b + chunk, n);
    int s = 0;
    for (int i = b; i < e; i++) {
        int h = g_hist[i];
        s += h;
        g_dis[i] = rsqrtf((float)(h + 1));
    }
    sums[tid] = s;
    __syncthreads();
    for (int off = 1; off < 1024; off <<= 1) {
        int v = (tid >= off) ? sums[tid - off] : 0;
        __syncthreads();
        sums[tid] += v;
        __syncthreads();
    }
    int run = (tid > 0) ? sums[tid - 1] : 0;
    for (int i = b; i < e; i++) { g_rowptr[i] = run; run += g_hist[i]; }
    if (b < n && e == n) g_rowptr[n] = run;
}

__global__ void scatter_kernel(const void* __restrict__ ei, int E) {
    int i = blockIdx.x * blockDim.x + threadIdx.x;
    if (i >= E) return;
    int d = load_idx(ei, E, 1, i);
    if (d < 0 || d >= MAXN) return;
    int s = load_idx(ei, E, 0, i);
    int pos = g_rowptr[d] + atomicAdd(&g_cnt[d], 1);
    if (pos >= 0 && pos < MAXE) g_esrc[pos] = s;
}

// ---------------- W1+W2 -> bf16 hi/lo chunk images -------------------------------
__global__ void convB_kernel(const float* __restrict__ W1, const float* __restrict__ W2) {
    int idx = blockIdx.x * blockDim.x + threadIdx.x;
    const float* W;
    int chunkBase;
    if (idx < 256 * 128) { W = W1; chunkBase = 0; }
    else if (idx < 256 * 128 + 128 * 128) { W = W2; chunkBase = 8; idx -= 256 * 128; }
    else return;
    int n = idx & 127;
    int k = idx >> 7;
    float v = W[(size_t)k * 128 + n];
    __nv_bfloat16 hb = __float2bfloat16(v);
    float lo = v - __bfloat162float(hb);
    __nv_bfloat16 lb = __float2bfloat16(lo);
    int c = k >> 5;
    int kl = k & 31;
    size_t base = (size_t)(chunkBase + c) * BCHUNK_BYTES + (size_t)kl * B_ROW_STRIDE + n * 2;
    *(unsigned short*)(g_bimg + base) = __bfloat16_as_ushort(hb);
    *(unsigned short*)(g_bimg + base + 8704) = __bfloat16_as_ushort(lb);
}

// ---------------- tensor-core GEMM via mma.sync: g_h = dis * (A @ W) -------------
// Split bf16: A@W ~= Ahi@Whi + Ahi@Wlo + Alo@Whi; fp32 register accumulators.
// CTA tile 128x128, 8 warps of 32x64; K in chunks of 32 (2 k16 steps).
// Pipelined: B via cp.async; A(c+1) prefetched to regs before MMA(c).
__global__ void __launch_bounds__(256)
gemm_mma(const float* __restrict__ Aext, int M, int K, int chunkBase) {
    __shared__ __align__(16) unsigned char As[2][128 * A_ROW_STRIDE];  // hi, lo
    __shared__ __align__(16) unsigned char Bs[2][32 * B_ROW_STRIDE];   // hi, lo (flat 17408 B)

    const float* A = Aext ? Aext : (const float*)g_x1;
    float* C = (float*)g_h;

    const int tid = threadIdx.x;
    const int wid = tid >> 5;
    const int lane = tid & 31;
    const int block_row = blockIdx.x * 128;
    const int mr = (wid & 3) * 32;
    const int nc = (wid >> 2) * 64;

    const uint32_t as_base = smem_u32(&As[0][0]);
    const uint32_t bs_base = smem_u32(&Bs[0][0]);

    const int a_lrow = lane & 15;
    const int a_lk16 = (lane >> 4) * 16;
    const int b_lk = (lane & 7) | (((lane >> 3) & 1) << 3);
    const int b_ln8 = (lane >> 4) * 8;

    // per-thread A fill coordinates (2 items of 8 floats)
    const int f_row0 = tid >> 2;               // 0..63
    const int f_row1 = (tid + 256) >> 2;       // 64..127
    const int f_kl = (tid & 3) << 3;           // 0,8,16,24

    float d[2][8][4];
#pragma unroll
    for (int mi = 0; mi < 2; mi++)
#pragma unroll
        for (int j = 0; j < 8; j++)
#pragma unroll
            for (int q = 0; q < 4; q++) d[mi][j][q] = 0.f;

    const int nchunks = K >> 5;
    float pv[2][8];

    // prefetch A chunk 0
#pragma unroll
    for (int i = 0; i < 2; i++) {
        int row = i ? f_row1 : f_row0;
        int gr = block_row + row;
#pragma unroll
        for (int j = 0; j < 8; j++) pv[i][j] = 0.f;
        if (gr < M) {
            const float* ap = A + (size_t)gr * K + f_kl;
            float4 a0 = *(const float4*)ap;
            float4 a1 = *(const float4*)(ap + 4);
            pv[i][0] = a0.x; pv[i][1] = a0.y; pv[i][2] = a0.z; pv[i][3] = a0.w;
            pv[i][4] = a1.x; pv[i][5] = a1.y; pv[i][6] = a1.z; pv[i][7] = a1.w;
        }
    }

    for (int c = 0; c < nchunks; c++) {
        // ---- kick off B chunk copy via cp.async (1088 x 16 B) ----
        {
            const uint4* src = (const uint4*)(g_bimg + (size_t)(chunkBase + c) * BCHUNK_BYTES);
#pragma unroll
            for (int k = 0; k < 5; k++) {
                int j = tid + k * 256;
                if (j < BCHUNK_BYTES / 16) cp16(bs_base + j * 16, src + j);
            }
            cp_commit();
        }
        // ---- convert prefetched A regs -> smem hi/lo ----
#pragma unroll
        for (int i = 0; i < 2; i++) {
            int row = i ? f_row1 : f_row0;
            unsigned short h[8], l[8];
#pragma unroll
            for (int j = 0; j < 8; j++) {
                __nv_bfloat16 hb = __float2bfloat16(pv[i][j]);
                float r = pv[i][j] - __bfloat162float(hb);
                h[j] = __bfloat16_as_ushort(hb);
                l[j] = __bfloat16_as_ushort(__float2bfloat16(r));
            }
            uint4 uh, ul;
            uh.x = (uint32_t)h[0] | ((uint32_t)h[1] << 16);
            uh.y = (uint32_t)h[2] | ((uint32_t)h[3] << 16);
            uh.z = (uint32_t)h[4] | ((uint32_t)h[5] << 16);
            uh.w = (uint32_t)h[6] | ((uint32_t)h[7] << 16);
            ul.x = (uint32_t)l[0] | ((uint32_t)l[1] << 16);
            ul.y = (uint32_t)l[2] | ((uint32_t)l[3] << 16);
            ul.z = (uint32_t)l[4] | ((uint32_t)l[5] << 16);
            ul.w = (uint32_t)l[6] | ((uint32_t)l[7] << 16);
            uint32_t off = (uint32_t)row * A_ROW_STRIDE + (uint32_t)f_kl * 2;
            *(uint4*)(&As[0][off]) = uh;
            *(uint4*)(&As[1][off]) = ul;
        }
        // ---- prefetch A chunk c+1 into regs (overlaps with MMA below) ----
        if (c + 1 < nchunks) {
#pragma unroll
            for (int i = 0; i < 2; i++) {
                int row = i ? f_row1 : f_row0;
                int gr = block_row + row;
#pragma unroll
                for (int j = 0; j < 8; j++) pv[i][j] = 0.f;
                if (gr < M) {
                    const float* ap = A + (size_t)gr * K + ((c + 1) << 5) + f_kl;
                    float4 a0 = *(const float4*)ap;
                    float4 a1 = *(const float4*)(ap + 4);
                    pv[i][0] = a0.x; pv[i][1] = a0.y; pv[i][2] = a0.z; pv[i][3] = a0.w;
                    pv[i][4] = a1.x; pv[i][5] = a1.y; pv[i][6] = a1.z; pv[i][7] = a1.w;
                }
            }
        }
        cp_wait0();
        __syncthreads();

        // ---- 2 k16 steps x 3 split terms ----
#pragma unroll
        for (int s = 0; s < 2; s++) {
            uint32_t ah[2][4], al[2][4];
#pragma unroll
            for (int mi = 0; mi < 2; mi++) {
                uint32_t arow = (uint32_t)(mr + mi * 16 + a_lrow) * A_ROW_STRIDE
                              + (uint32_t)s * 32 + a_lk16;
                ldsm4(ah[mi], as_base + arow);
                ldsm4(al[mi], as_base + 128 * A_ROW_STRIDE + arow);
            }
#pragma unroll
            for (int t = 0; t < 4; t++) {
                uint32_t boff = (uint32_t)(s * 16 + b_lk) * B_ROW_STRIDE
                              + (uint32_t)(nc + t * 16 + b_ln8) * 2;
                uint32_t bh[4], bl[4];
                ldsm4t(bh, bs_base + boff);
                ldsm4t(bl, bs_base + 32 * B_ROW_STRIDE + boff);
#pragma unroll
                for (int mi = 0; mi < 2; mi++) {
                    mma_bf16(d[mi][2 * t],     ah[mi], bh);       // hi*hi
                    mma_bf16(d[mi][2 * t + 1], ah[mi], bh + 2);
                    mma_bf16(d[mi][2 * t],     ah[mi], bl);       // hi*lo
                    mma_bf16(d[mi][2 * t + 1], ah[mi], bl + 2);
                    mma_bf16(d[mi][2 * t],     al[mi], bh);       // lo*hi
                    mma_bf16(d[mi][2 * t + 1], al[mi], bh + 2);
                }
            }
        }
        __syncthreads();
    }

    // ---- epilogue: scale by dis[row], store fp32 ----
#pragma unroll
    for (int mi = 0; mi < 2; mi++) {
        int r0 = block_row + mr + mi * 16 + (lane >> 2);
        int r1 = r0 + 8;
        float s0 = (r0 < M) ? g_dis[r0] : 0.f;
        float s1 = (r1 < M) ? g_dis[r1] : 0.f;
#pragma unroll
        for (int j = 0; j < 8; j++) {
            int col = nc + j * 8 + (lane & 3) * 2;
            if (r0 < M) {
                float2 v = make_float2(d[mi][j][0] * s0, d[mi][j][1] * s0);
                *(float2*)(C + (size_t)r0 * 128 + col) = v;
            }
            if (r1 < M) {
                float2 v = make_float2(d[mi][j][2] * s1, d[mi][j][3] * s1);
                *(float2*)(C + (size_t)r1 * 128 + col) = v;
            }
        }
    }
}

// ---------------- aggregation: out[i] = act(dis[i]*(hs[i] + sum hs[src]) + bias) ----
// one warp per node; inner loop unrolled x4 for memory-level parallelism
__global__ void __launch_bounds__(256)
agg_kernel(const float* __restrict__ bias, float* __restrict__ outExt,
           int N, int doRelu) {
    const float* hs = (const float*)g_h;
    float* out = outExt ? outExt : (float*)g_x1;

    int w = (blockIdx.x * blockDim.x + threadIdx.x) >> 5;
    int lane = threadIdx.x & 31;
    if (w >= N) return;

    const float4* hsv = (const float4*)hs;
    float4 acc = hsv[(size_t)w * 32 + lane];  // self loop
    int s0 = g_rowptr[w], s1 = g_rowptr[w + 1];
    for (int e0 = s0; e0 < s1; e0 += 32) {
        int cnt = min(32, s1 - e0);
        int sidx = 0;
        if (lane < cnt) sidx = g_esrc[e0 + lane];
        int j = 0;
        for (; j + 4 <= cnt; j += 4) {
            int i0 = __shfl_sync(0xffffffffu, sidx, j);
            int i1 = __shfl_sync(0xffffffffu, sidx, j + 1);
            int i2 = __shfl_sync(0xffffffffu, sidx, j + 2);
            int i3 = __shfl_sync(0xffffffffu, sidx, j + 3);
            float4 v0 = hsv[(size_t)i0 * 32 + lane];
            float4 v1 = hsv[(size_t)i1 * 32 + lane];
            float4 v2 = hsv[(size_t)i2 * 32 + lane];
            float4 v3 = hsv[(size_t)i3 * 32 + lane];
            acc.x += (v0.x + v1.x) + (v2.x + v3.x);
            acc.y += (v0.y + v1.y) + (v2.y + v3.y);
            acc.z += (v0.z + v1.z) + (v2.z + v3.z);
            acc.w += (v0.w + v1.w) + (v2.w + v3.w);
        }
        for (; j < cnt; j++) {
            int s = __shfl_sync(0xffffffffu, sidx, j);
            float4 v = hsv[(size_t)s * 32 + lane];
            acc.x += v.x; acc.y += v.y; acc.z += v.z; acc.w += v.w;
        }
    }
    float d = g_dis[w];
    float4 b = *((const float4*)bias + lane);
    float4 r;
    r.x = fmaf(d, acc.x, b.x);
    r.y = fmaf(d, acc.y, b.y);
    r.z = fmaf(d, acc.z, b.z);
    r.w = fmaf(d, acc.w, b.w);
    if (doRelu) {
        r.x = fmaxf(r.x, 0.f); r.y = fmaxf(r.y, 0.f);
        r.z = fmaxf(r.z, 0.f); r.w = fmaxf(r.w, 0.f);
    }
    *((float4*)(out + (size_t)w * DH) + lane) = r;
}

// ---------------- launch ----------------
extern "C" void kernel_launch(void* const* d_in, const int* in_sizes, int n_in,
                              void* d_out, int out_size) {
    const float* x  = (const float*)d_in[0];      // [N, 256]
    const void*  ei = d_in[1];                    // [2, E] int64 OR int32
    const float* W1 = (const float*)d_in[2];      // [256, 128]
    const float* b1 = (const float*)d_in[3];      // [128]
    const float* W2 = (const float*)d_in[4];      // [128, 128]
    const float* b2 = (const float*)d_in[5];      // [128]
    float* out = (float*)d_out;

    int N = in_sizes[0] / 256;
    int E = in_sizes[1] / 2;
    int eblocks = (E + 255) / 256;

    // graph preprocessing (zero+detect, histogram, scan+dis, CSR scatter)
    init_kernel<<<(N + 255) / 256, 256>>>((const int*)ei, E, N);
    hist_kernel<<<eblocks, 256>>>(ei, E);
    scan_kernel<<<1, 1024>>>(N);
    scatter_kernel<<<eblocks, 256>>>(ei, E);

    // weight preconversion to bf16 hi/lo chunk images (both layers, one kernel)
    convB_kernel<<<(256 * 128 + 128 * 128 + 255) / 256, 256>>>(W1, W2);

    int gblocks = (N + 127) / 128;
    // layer 1: g_h = dis*(x@W1); g_x1 = relu(dis*(gather-sum)+b1)
    gemm_mma<<<gblocks, 256>>>(x, N, 256, 0);
    agg_kernel<<<(N + 7) / 8, 256>>>(b1, nullptr, N, 1);

    // layer 2: g_h = dis*(x1@W2); out = dis*(gather-sum)+b2
    gemm_mma<<<gblocks, 256>>>(nullptr, N, 128, 8);
    agg_kernel<<<(N + 7) / 8, 256>>>(b2, out, N, 0);
}